// round 10
// baseline (speedup 1.0000x reference)
#include <cuda_runtime.h>
#include <cuda_fp16.h>

#define NN 100000
#define NE 3200000
#define HH 32
#define EMBD 16

// ---------------- device scratch (static, no allocation) ----------------
__device__ __half   g_h[NN * HH];     // layer-1 features (fp16)
__device__ float    g_hs[NN];         // layer-1 h·as
__device__ float    g_hd[NN];         // layer-1 h·ad, overwritten with layer-2 h2·ad2
__device__ float    g_loop[NN];       // self-loop attr
__device__ float2   g_sp[NN];         // layer-2 (h2·as2, h2·Wl)
__device__ int      g_cnt[NN];        // degree histogram
__device__ int      g_ptr[NN + 1];    // CSR row pointers
__device__ int      g_cur[NN];        // scatter cursors
__device__ float2   g_csr[NE];        // (src as int bits, ea)
__device__ float    g_ce[3];          // ce1, ce2, b2·Wl + bl
__device__ float    g_cs[HH];         // W2 · as2
__device__ float    g_cd[HH];         // W2 · ad2
__device__ float    g_cp[HH];         // W2 · Wl

// ---------------- kernels ----------------

__global__ void k_init(const float* We1, const float* ae1,
                       const float* We2, const float* ae2,
                       const float* b2,  const float* Wl, const float* bl,
                       const float* W2,  const float* as2, const float* ad2) {
    int i = blockIdx.x * blockDim.x + threadIdx.x;
    if (i == 0) {
        float c = 0.f;
        for (int j = 0; j < HH; j++) c += We1[j] * ae1[j];
        g_ce[0] = c;
    }
    if (i == 1) {
        float c = 0.f;
        for (int j = 0; j < HH; j++) c += We2[j] * ae2[j];
        g_ce[1] = c;
    }
    if (i == 2) {
        float c = bl[0];
        for (int j = 0; j < HH; j++) c += b2[j] * Wl[j];
        g_ce[2] = c;
    }
    if (i >= 32 && i < 32 + HH) {
        int k = i - 32;
        float cs = 0.f, cd = 0.f, cp = 0.f;
        const float* wr = W2 + k * HH;
        for (int j = 0; j < HH; j++) {
            float w = wr[j];
            cs = fmaf(w, as2[j], cs);
            cd = fmaf(w, ad2[j], cd);
            cp = fmaf(w, Wl[j],  cp);
        }
        g_cs[k] = cs; g_cd[k] = cd; g_cp[k] = cp;
    }
}

__global__ void k_zcnt() {
    int i = blockIdx.x * blockDim.x + threadIdx.x;
    if (i < NN) g_cnt[i] = 0;
}

__global__ void k_hist(const int* __restrict__ dst) {
    int e = blockIdx.x * blockDim.x + threadIdx.x;
    if (e >= NE) return;
    atomicAdd(&g_cnt[dst[e]], 1);
}

// single-block exclusive scan over g_cnt -> g_ptr, g_cur
__global__ void k_scan() {
    const int T = 1024;
    __shared__ int sh[T];
    int t = threadIdx.x;
    const int chunk = (NN + T - 1) / T;
    int base = t * chunk;
    int lim = base + chunk; if (lim > NN) lim = NN;
    int sum = 0;
    for (int i = base; i < lim; i++) sum += g_cnt[i];
    sh[t] = sum;
    __syncthreads();
    for (int off = 1; off < T; off <<= 1) {
        int v = (t >= off) ? sh[t - off] : 0;
        __syncthreads();
        sh[t] += v;
        __syncthreads();
    }
    int run = sh[t] - sum;  // exclusive prefix of this chunk
    for (int i = base; i < lim; i++) {
        g_ptr[i] = run; g_cur[i] = run;
        run += g_cnt[i];
    }
    if (t == T - 1) g_ptr[NN] = NE;
}

// scatter edges into dst-bucketed CSR: entry = (src bits, ea)
__global__ void k_scat(const int* __restrict__ src, const int* __restrict__ dst,
                       const float* __restrict__ ea) {
    int e = blockIdx.x * blockDim.x + threadIdx.x;
    if (e >= NE) return;
    int d = dst[e];
    int pos = atomicAdd(&g_cur[d], 1);
    g_csr[pos] = make_float2(__int_as_float(src[e]), ea[e]);
}

// layer-1 node pass: h = emb[x_idx] @ W1 (fp16), hs/hd
__global__ void k_h1(const int* __restrict__ x_idx, const float* __restrict__ emb,
                     const float* __restrict__ W1, const float* __restrict__ as1,
                     const float* __restrict__ ad1) {
    __shared__ float sW[EMBD * HH];
    __shared__ float sas[HH], sad[HH];
    int t = threadIdx.x;
    for (int i = t; i < EMBD * HH; i += blockDim.x) sW[i] = W1[i];
    if (t < HH) { sas[t] = as1[t]; sad[t] = ad1[t]; }
    __syncthreads();
    int n = (blockIdx.x * blockDim.x + t) >> 5;
    int lane = t & 31;
    if (n >= NN) return;
    int idx = x_idx[n];
    const float* xr = emb + idx * EMBD;
    float acc = 0.f;
#pragma unroll
    for (int k = 0; k < EMBD; k++) acc = fmaf(xr[k], sW[k * HH + lane], acc);
    g_h[n * HH + lane] = __float2half(acc);
    float s = acc * sas[lane];
    float d = acc * sad[lane];
    for (int o = 16; o; o >>= 1) {
        s += __shfl_xor_sync(0xffffffffu, s, o);
        d += __shfl_xor_sync(0xffffffffu, d, o);
    }
    if (lane == 0) { g_hs[n] = s; g_hd[n] = d; }
}

// layer-1 aggregation, warp per dst: register accumulation, NO atomics.
// Fused: GAT softmax-aggregate + self-loop + bias + relu + collapsed layer-2 projections.
__global__ void k_agg1(const float* __restrict__ b1) {
    int t = threadIdx.x;
    int n = (blockIdx.x * blockDim.x + t) >> 5;
    int lane = t & 31;
    if (n >= NN) return;
    int start = g_ptr[n], end = g_ptr[n + 1];
    float ce0 = g_ce[0];
    float hdn = g_hd[n];
    float accF = 0.f, den = 0.f, sumea = 0.f;
#pragma unroll 4
    for (int i = start; i < end; i++) {
        float2 eg = g_csr[i];                 // uniform across warp
        int s   = __float_as_int(eg.x);
        float a = eg.y;
        float al = g_hs[s] + hdn + a * ce0;   // uniform load
        al = (al > 0.f) ? al : 0.2f * al;
        float ex = __expf(al);
        float hv = __half2float(g_h[s * HH + lane]);  // 64B coalesced gather
        accF = fmaf(ex, hv, accF);
        den += ex; sumea += a;
    }
    float deg  = (float)(end - start);
    float loop = sumea / fmaxf(deg, 1.f);
    float al = g_hs[n] + hdn + loop * ce0;
    al = (al > 0.f) ? al : 0.2f * al;
    float exs = __expf(al);
    float hn = __half2float(g_h[n * HH + lane]);
    float v = (accF + exs * hn) / (den + exs + 1e-16f);
    v = fmaxf(v + b1[lane], 0.f);
    float s2 = v * g_cs[lane];
    float d2 = v * g_cd[lane];
    float p  = v * g_cp[lane];
    for (int o = 16; o; o >>= 1) {
        s2 += __shfl_xor_sync(0xffffffffu, s2, o);
        d2 += __shfl_xor_sync(0xffffffffu, d2, o);
        p  += __shfl_xor_sync(0xffffffffu, p,  o);
    }
    if (lane == 0) {
        g_sp[n] = make_float2(s2, p);
        g_hd[n] = d2;
        g_loop[n] = loop;
    }
}

// layer-2 aggregation, warp per dst, lanes stride the edge list; fused final output.
__global__ void k_agg2(float* __restrict__ out) {
    int t = threadIdx.x;
    int n = (blockIdx.x * blockDim.x + t) >> 5;
    int lane = t & 31;
    if (n >= NN) return;
    int start = g_ptr[n], end = g_ptr[n + 1];
    float ce1 = g_ce[1];
    float hdn = g_hd[n];
    float num = 0.f, den = 0.f;
    for (int i = start + lane; i < end; i += 32) {
        float2 eg = g_csr[i];                 // coalesced within bucket
        int s   = __float_as_int(eg.x);
        float a = eg.y;
        float2 sp = g_sp[s];                  // 8B gather
        float al = sp.x + hdn + a * ce1;
        al = (al > 0.f) ? al : 0.2f * al;
        float ex = __expf(al);
        num = fmaf(ex, sp.y, num);
        den += ex;
    }
    for (int o = 16; o; o >>= 1) {
        num += __shfl_xor_sync(0xffffffffu, num, o);
        den += __shfl_xor_sync(0xffffffffu, den, o);
    }
    if (lane == 0) {
        float2 spn = g_sp[n];
        float al = spn.x + hdn + g_loop[n] * ce1;
        al = (al > 0.f) ? al : 0.2f * al;
        float exs = __expf(al);
        out[n] = (num + exs * spn.y) / (den + exs + 1e-16f) + g_ce[2];
    }
}

// ---------------- launch ----------------
extern "C" void kernel_launch(void* const* d_in, const int* in_sizes, int n_in,
                              void* d_out, int out_size) {
    const int*   x_idx = (const int*)  d_in[0];
    const int*   ei    = (const int*)  d_in[1];
    const float* ea    = (const float*)d_in[2];
    const float* emb   = (const float*)d_in[3];
    const float* W1    = (const float*)d_in[4];
    const float* as1   = (const float*)d_in[5];
    const float* ad1   = (const float*)d_in[6];
    const float* We1   = (const float*)d_in[7];
    const float* ae1   = (const float*)d_in[8];
    const float* b1    = (const float*)d_in[9];
    const float* W2    = (const float*)d_in[10];
    const float* as2   = (const float*)d_in[11];
    const float* ad2   = (const float*)d_in[12];
    const float* We2   = (const float*)d_in[13];
    const float* ae2   = (const float*)d_in[14];
    const float* b2    = (const float*)d_in[15];
    const float* Wl    = (const float*)d_in[16];
    const float* bl    = (const float*)d_in[17];
    float* out = (float*)d_out;

    const int* src = ei;
    const int* dst = ei + NE;

    const int TB = 256;
    const int gN  = (NN + TB - 1) / TB;
    const int gE  = (NE + TB - 1) / TB;
    const int gNW = (NN * 32 + TB - 1) / TB;   // warp per node

    // CSR build
    k_init<<<1, 64>>>(We1, ae1, We2, ae2, b2, Wl, bl, W2, as2, ad2);
    k_zcnt<<<gN, TB>>>();
    k_hist<<<gE, TB>>>(dst);
    k_scan<<<1, 1024>>>();
    k_h1<<<gNW, TB>>>(x_idx, emb, W1, as1, ad1);
    k_scat<<<gE, TB>>>(src, dst, ea);

    // layer 1 (fused aggregate + mid)
    k_agg1<<<gNW, TB>>>(b1);
    // layer 2 (fused aggregate + final)
    k_agg2<<<gNW, TB>>>(out);
}

// round 11
// speedup vs baseline: 1.6883x; 1.6883x over previous
#include <cuda_runtime.h>
#include <cuda_fp16.h>

#define NN 100000
#define NE 3200000
#define HH 32
#define EMBD 16
#define NBLK 98   // ceil(NN/1024)

// ---------------- device scratch (static, no allocation) ----------------
__device__ __half   g_h[NN * HH];     // layer-1 features (fp16)
__device__ float    g_hs[NN];         // layer-1 h·as
__device__ float    g_hd[NN];         // layer-1 h·ad, overwritten with layer-2 h2·ad2
__device__ float    g_loop[NN];       // self-loop attr
__device__ float2   g_sp[NN];         // layer-2 (h2·as2, h2·Wl)
__device__ int      g_cnt[NN];        // degree histogram
__device__ int      g_ptr[NN + 1];    // CSR row pointers
__device__ int      g_cur[NN];        // scatter cursors
__device__ int      g_bsum[NBLK];     // per-block scan totals
__device__ int      g_boff[NBLK];     // per-block scan offsets
__device__ float2   g_csr[NE];        // (src as int bits, ea)
__device__ float    g_ce[3];          // ce1, ce2, b2·Wl + bl
__device__ float    g_cs[HH];         // W2 · as2
__device__ float    g_cd[HH];         // W2 · ad2
__device__ float    g_cp[HH];         // W2 · Wl

// ---------------- kernels ----------------

__global__ void k_init(const float* We1, const float* ae1,
                       const float* We2, const float* ae2,
                       const float* b2,  const float* Wl, const float* bl,
                       const float* W2,  const float* as2, const float* ad2) {
    int i = blockIdx.x * blockDim.x + threadIdx.x;
    if (i == 0) {
        float c = 0.f;
        for (int j = 0; j < HH; j++) c += We1[j] * ae1[j];
        g_ce[0] = c;
    }
    if (i == 1) {
        float c = 0.f;
        for (int j = 0; j < HH; j++) c += We2[j] * ae2[j];
        g_ce[1] = c;
    }
    if (i == 2) {
        float c = bl[0];
        for (int j = 0; j < HH; j++) c += b2[j] * Wl[j];
        g_ce[2] = c;
    }
    if (i >= 32 && i < 32 + HH) {
        int k = i - 32;
        float cs = 0.f, cd = 0.f, cp = 0.f;
        const float* wr = W2 + k * HH;
        for (int j = 0; j < HH; j++) {
            float w = wr[j];
            cs = fmaf(w, as2[j], cs);
            cd = fmaf(w, ad2[j], cd);
            cp = fmaf(w, Wl[j],  cp);
        }
        g_cs[k] = cs; g_cd[k] = cd; g_cp[k] = cp;
    }
}

__global__ void k_zcnt() {
    int i = blockIdx.x * blockDim.x + threadIdx.x;
    if (i < NN) g_cnt[i] = 0;
}

__global__ void k_hist(const int* __restrict__ dst) {
    int e = blockIdx.x * blockDim.x + threadIdx.x;
    if (e >= NE) return;
    atomicAdd(&g_cnt[dst[e]], 1);
}

// stage A: per-block exclusive scan (1024 elems/block) via warp shuffles
__global__ void k_scanA() {
    __shared__ int swarp[32];
    int tid = threadIdx.x;
    int gid = blockIdx.x * 1024 + tid;
    int lane = tid & 31, wid = tid >> 5;
    int v = (gid < NN) ? g_cnt[gid] : 0;
    int x = v;
#pragma unroll
    for (int o = 1; o < 32; o <<= 1) {
        int y = __shfl_up_sync(0xffffffffu, x, o);
        if (lane >= o) x += y;
    }
    if (lane == 31) swarp[wid] = x;
    __syncthreads();
    if (wid == 0) {
        int s = swarp[lane];
#pragma unroll
        for (int o = 1; o < 32; o <<= 1) {
            int y = __shfl_up_sync(0xffffffffu, s, o);
            if (lane >= o) s += y;
        }
        swarp[lane] = s;
    }
    __syncthreads();
    int woff = wid ? swarp[wid - 1] : 0;
    if (gid < NN) g_ptr[gid] = woff + x - v;      // block-local exclusive
    if (tid == 1023) g_bsum[blockIdx.x] = swarp[31];
}

// stage B: scan the 98 block totals (one tiny block)
__global__ void k_scanB() {
    __shared__ int sh[128];
    int t = threadIdx.x;
    int v = (t < NBLK) ? g_bsum[t] : 0;
    sh[t] = v;
    __syncthreads();
    for (int o = 1; o < 128; o <<= 1) {
        int y = (t >= o) ? sh[t - o] : 0;
        __syncthreads();
        sh[t] += y;
        __syncthreads();
    }
    if (t < NBLK) g_boff[t] = sh[t] - v;          // exclusive
}

// stage C: add block offsets, init cursors
__global__ void k_scanC() {
    int gid = blockIdx.x * 1024 + threadIdx.x;
    if (gid < NN) {
        int p = g_ptr[gid] + g_boff[blockIdx.x];
        g_ptr[gid] = p;
        g_cur[gid] = p;
    }
    if (gid == 0) g_ptr[NN] = NE;
}

// scatter edges into dst-bucketed CSR: entry = (src bits, ea)
__global__ void k_scat(const int* __restrict__ src, const int* __restrict__ dst,
                       const float* __restrict__ ea) {
    int e = blockIdx.x * blockDim.x + threadIdx.x;
    if (e >= NE) return;
    int d = dst[e];
    int pos = atomicAdd(&g_cur[d], 1);
    g_csr[pos] = make_float2(__int_as_float(src[e]), ea[e]);
}

// layer-1 node pass: h = emb[x_idx] @ W1 (fp16), hs/hd
__global__ void k_h1(const int* __restrict__ x_idx, const float* __restrict__ emb,
                     const float* __restrict__ W1, const float* __restrict__ as1,
                     const float* __restrict__ ad1) {
    __shared__ float sW[EMBD * HH];
    __shared__ float sas[HH], sad[HH];
    int t = threadIdx.x;
    for (int i = t; i < EMBD * HH; i += blockDim.x) sW[i] = W1[i];
    if (t < HH) { sas[t] = as1[t]; sad[t] = ad1[t]; }
    __syncthreads();
    int n = (blockIdx.x * blockDim.x + t) >> 5;
    int lane = t & 31;
    if (n >= NN) return;
    int idx = x_idx[n];
    const float* xr = emb + idx * EMBD;
    float acc = 0.f;
#pragma unroll
    for (int k = 0; k < EMBD; k++) acc = fmaf(xr[k], sW[k * HH + lane], acc);
    g_h[n * HH + lane] = __float2half(acc);
    float s = acc * sas[lane];
    float d = acc * sad[lane];
    for (int o = 16; o; o >>= 1) {
        s += __shfl_xor_sync(0xffffffffu, s, o);
        d += __shfl_xor_sync(0xffffffffu, d, o);
    }
    if (lane == 0) { g_hs[n] = s; g_hd[n] = d; }
}

// layer-1 aggregation, warp per dst: register accumulation, NO atomics.
// Fused: softmax-aggregate + self-loop + bias + relu + collapsed layer-2 projections.
__global__ void k_agg1(const float* __restrict__ b1) {
    int t = threadIdx.x;
    int n = (blockIdx.x * blockDim.x + t) >> 5;
    int lane = t & 31;
    if (n >= NN) return;
    int start = g_ptr[n], end = g_ptr[n + 1];
    float ce0 = g_ce[0];
    float hdn = g_hd[n];
    float accF = 0.f, den = 0.f, sumea = 0.f;
#pragma unroll 4
    for (int i = start; i < end; i++) {
        float2 eg = g_csr[i];                 // uniform across warp
        int s   = __float_as_int(eg.x);
        float a = eg.y;
        float al = g_hs[s] + hdn + a * ce0;   // uniform load
        al = (al > 0.f) ? al : 0.2f * al;
        float ex = __expf(al);
        float hv = __half2float(g_h[s * HH + lane]);  // 64B coalesced gather
        accF = fmaf(ex, hv, accF);
        den += ex; sumea += a;
    }
    float deg  = (float)(end - start);
    float loop = sumea / fmaxf(deg, 1.f);
    float al = g_hs[n] + hdn + loop * ce0;
    al = (al > 0.f) ? al : 0.2f * al;
    float exs = __expf(al);
    float hn = __half2float(g_h[n * HH + lane]);
    float v = (accF + exs * hn) / (den + exs + 1e-16f);
    v = fmaxf(v + b1[lane], 0.f);
    float s2 = v * g_cs[lane];
    float d2 = v * g_cd[lane];
    float p  = v * g_cp[lane];
    for (int o = 16; o; o >>= 1) {
        s2 += __shfl_xor_sync(0xffffffffu, s2, o);
        d2 += __shfl_xor_sync(0xffffffffu, d2, o);
        p  += __shfl_xor_sync(0xffffffffu, p,  o);
    }
    if (lane == 0) {
        g_sp[n] = make_float2(s2, p);
        g_hd[n] = d2;
        g_loop[n] = loop;
    }
}

// layer-2 aggregation, warp per dst, lanes stride the edge list; fused final output.
__global__ void k_agg2(float* __restrict__ out) {
    int t = threadIdx.x;
    int n = (blockIdx.x * blockDim.x + t) >> 5;
    int lane = t & 31;
    if (n >= NN) return;
    int start = g_ptr[n], end = g_ptr[n + 1];
    float ce1 = g_ce[1];
    float hdn = g_hd[n];
    float num = 0.f, den = 0.f;
    for (int i = start + lane; i < end; i += 32) {
        float2 eg = g_csr[i];                 // coalesced within bucket
        int s   = __float_as_int(eg.x);
        float a = eg.y;
        float2 sp = g_sp[s];                  // 8B gather
        float al = sp.x + hdn + a * ce1;
        al = (al > 0.f) ? al : 0.2f * al;
        float ex = __expf(al);
        num = fmaf(ex, sp.y, num);
        den += ex;
    }
    for (int o = 16; o; o >>= 1) {
        num += __shfl_xor_sync(0xffffffffu, num, o);
        den += __shfl_xor_sync(0xffffffffu, den, o);
    }
    if (lane == 0) {
        float2 spn = g_sp[n];
        float al = spn.x + hdn + g_loop[n] * ce1;
        al = (al > 0.f) ? al : 0.2f * al;
        float exs = __expf(al);
        out[n] = (num + exs * spn.y) / (den + exs + 1e-16f) + g_ce[2];
    }
}

// ---------------- launch ----------------
extern "C" void kernel_launch(void* const* d_in, const int* in_sizes, int n_in,
                              void* d_out, int out_size) {
    const int*   x_idx = (const int*)  d_in[0];
    const int*   ei    = (const int*)  d_in[1];
    const float* ea    = (const float*)d_in[2];
    const float* emb   = (const float*)d_in[3];
    const float* W1    = (const float*)d_in[4];
    const float* as1   = (const float*)d_in[5];
    const float* ad1   = (const float*)d_in[6];
    const float* We1   = (const float*)d_in[7];
    const float* ae1   = (const float*)d_in[8];
    const float* b1    = (const float*)d_in[9];
    const float* W2    = (const float*)d_in[10];
    const float* as2   = (const float*)d_in[11];
    const float* ad2   = (const float*)d_in[12];
    const float* We2   = (const float*)d_in[13];
    const float* ae2   = (const float*)d_in[14];
    const float* b2    = (const float*)d_in[15];
    const float* Wl    = (const float*)d_in[16];
    const float* bl    = (const float*)d_in[17];
    float* out = (float*)d_out;

    const int* src = ei;
    const int* dst = ei + NE;

    const int TB = 256;
    const int gN  = (NN + TB - 1) / TB;
    const int gE  = (NE + TB - 1) / TB;
    const int gNW = (NN * 32 + TB - 1) / TB;   // warp per node

    // CSR build
    k_init<<<1, 64>>>(We1, ae1, We2, ae2, b2, Wl, bl, W2, as2, ad2);
    k_zcnt<<<gN, TB>>>();
    k_hist<<<gE, TB>>>(dst);
    k_scanA<<<NBLK, 1024>>>();
    k_scanB<<<1, 128>>>();
    k_scanC<<<NBLK, 1024>>>();
    k_h1<<<gNW, TB>>>(x_idx, emb, W1, as1, ad1);
    k_scat<<<gE, TB>>>(src, dst, ea);

    // layer 1 (fused aggregate + mid)
    k_agg1<<<gNW, TB>>>(b1);
    // layer 2 (fused aggregate + final)
    k_agg2<<<gNW, TB>>>(out);
}